// round 14
// baseline (speedup 1.0000x reference)
#include <cuda_runtime.h>
#include <cuda_fp16.h>
#include <cstdint>
#include <cstddef>

// ============================================================================
// RPNHead: single-pass fp16 mma.sync implicit GEMM (K=2304), CTA 128x256,
// 8 warps / warp-tile 64x64, K-stage 64, 3-stage cp.async, 1 sync/stage,
// register-fragment double buffering; cp.async issued AFTER frag preload.
// Heads fused into conv epilogue; finalize sums + softmax + scatter.
// cvt: 8x float4 per thread (MLP 8).
// ============================================================================

#define TOTM     174592
#define TOT_POS  261888
#define KTOT     2304            // 9 * 256
#define NSTAGE   36              // KTOT / 64

// conv smem: rows of 64 fp16 = 128B + 16B pad = 144B pitch
#define ROW_P    144
#define A_TILE_B (128 * ROW_P)   // 18432
#define B_TILE_B (256 * ROW_P)   // 36864
#define STAGE_B  (A_TILE_B + B_TILE_B)   // 55296
#define SMEM_DYN (3 * STAGE_B)           // 165888

// epilogue smem layout (reuses stage buffers)
#define EP_PITCH 528             // 264 halfs: 256 data + 8 pad
#define WH_OFF   67584           // after ep tile 128*528

__device__ __align__(16) __half g_x16[(size_t)TOTM * 256];
__device__ __align__(16) __half g_wT [(size_t)512 * KTOT];
__device__ __align__(16) __half g_wh [24 * 512];
__device__ float g_part[2][(size_t)TOTM * 18];

// ---------------------------------------------------------------------------
__device__ __forceinline__ uint32_t smem_u32(const void* p) {
    uint32_t a;
    asm("{ .reg .u64 t; cvta.to.shared.u64 t, %1; cvt.u32.u64 %0, t; }"
        : "=r"(a) : "l"(p));
    return a;
}
__device__ __forceinline__ void cp_async16(uint32_t dst, const void* src, int sz) {
    asm volatile("cp.async.ca.shared.global [%0], [%1], 16, %2;"
                 :: "r"(dst), "l"(src), "r"(sz) : "memory");
}
__device__ __forceinline__ void cp_commit() {
    asm volatile("cp.async.commit_group;" ::: "memory");
}
__device__ __forceinline__ void cp_wait1() {
    asm volatile("cp.async.wait_group 1;" ::: "memory");
}
__device__ __forceinline__ void ldm_x4(uint32_t* r, uint32_t addr) {
    asm volatile("ldmatrix.sync.aligned.m8n8.x4.shared.b16 {%0,%1,%2,%3}, [%4];"
                 : "=r"(r[0]), "=r"(r[1]), "=r"(r[2]), "=r"(r[3]) : "r"(addr));
}
__device__ __forceinline__ void ldm_x2(uint32_t* r, uint32_t addr) {
    asm volatile("ldmatrix.sync.aligned.m8n8.x2.shared.b16 {%0,%1}, [%2];"
                 : "=r"(r[0]), "=r"(r[1]) : "r"(addr));
}
__device__ __forceinline__ void mma16816(float* c, const uint32_t* a,
                                         uint32_t b0, uint32_t b1) {
    asm volatile(
        "mma.sync.aligned.m16n8k16.row.col.f32.f16.f16.f32 "
        "{%0,%1,%2,%3}, {%4,%5,%6,%7}, {%8,%9}, {%0,%1,%2,%3};"
        : "+f"(c[0]), "+f"(c[1]), "+f"(c[2]), "+f"(c[3])
        : "r"(a[0]), "r"(a[1]), "r"(a[2]), "r"(a[3]), "r"(b0), "r"(b1));
}

__device__ __forceinline__ int lvl_of_blk(int mb) {
    return (mb >= 1360) ? 4 : (mb >= 1344) ? 3 : (mb >= 1280) ? 2
         : (mb >= 1024) ? 1 : 0;
}
__device__ __forceinline__ int lvl_of_pix(int gp) {
    return (gp >= 174080) ? 4 : (gp >= 172032) ? 3 : (gp >= 163840) ? 2
         : (gp >= 131072) ? 1 : 0;
}
__constant__ int c_H[5]      = {256, 128, 64, 32, 16};
__constant__ int c_pixB[5]   = {0, 131072, 163840, 172032, 174080};
__constant__ int c_blkB[5]   = {0, 1024, 1280, 1344, 1360};
__constant__ int c_posOff[5] = {0, 196608, 245760, 258048, 261120};

// ---------------------------------------------------------------------------
// merged conversion kernel: x (8x float4/thread, MLP 8) + w_share^T + w_heads
// index space: [0, TOTM*8) = x octs ; next 294912 = wT ; next 512 = wh cols
// ---------------------------------------------------------------------------
#define CVT_XO   (TOTM * 8)                // 1396736 octs (each = 8 float4)
#define CVT_WV   (512 * KTOT / 4)          // 294912
#define CVT_TOT  (CVT_XO + CVT_WV + 512)

__global__ __launch_bounds__(256)
void cvt_all_kernel(const float* __restrict__ x0, const float* __restrict__ x1,
                    const float* __restrict__ x2, const float* __restrict__ x3,
                    const float* __restrict__ x4,
                    const float* __restrict__ wsh,
                    const float* __restrict__ wcls, const float* __restrict__ wbox)
{
    int i = blockIdx.x * 256 + threadIdx.x;
    if (i < CVT_XO) {
        // oct i covers float4s 8i..8i+7 (one pixel spans 64 float4s, so an
        // oct never crosses a level boundary)
        int l = (i >= 174080 * 8) ? 4 : (i >= 172032 * 8) ? 3
              : (i >= 163840 * 8) ? 2 : (i >= 131072 * 8) ? 1 : 0;
        const float* xs[5] = {x0, x1, x2, x3, x4};
        const float4* src = reinterpret_cast<const float4*>(xs[l])
                          + ((size_t)i * 8 - (size_t)c_pixB[l] * 64);
        float4 v[8];
#pragma unroll
        for (int j = 0; j < 8; j++) v[j] = src[j];      // MLP 8: all loads first
        uint32_t r[16];
#pragma unroll
        for (int j = 0; j < 8; j++) {
            __half2 h01 = __floats2half2_rn(v[j].x, v[j].y);
            __half2 h23 = __floats2half2_rn(v[j].z, v[j].w);
            r[j * 2]     = *reinterpret_cast<uint32_t*>(&h01);
            r[j * 2 + 1] = *reinterpret_cast<uint32_t*>(&h23);
        }
        uint4* dst = reinterpret_cast<uint4*>(g_x16 + (size_t)i * 32);
#pragma unroll
        for (int j = 0; j < 4; j++)
            dst[j] = make_uint4(r[j * 4], r[j * 4 + 1], r[j * 4 + 2], r[j * 4 + 3]);
    } else if (i < CVT_XO + CVT_WV) {
        int j4 = i - CVT_XO;                 // 4 consecutive k's of one n
        int n = (j4 * 4) / KTOT, k = (j4 * 4) - n * KTOT;
#pragma unroll
        for (int t = 0; t < 4; t++)
            g_wT[(size_t)n * KTOT + k + t] =
                __float2half_rn(wsh[(size_t)(k + t) * 512 + n]);
    } else if (i < CVT_TOT) {
        int c = i - CVT_XO - CVT_WV;         // 0..511
#pragma unroll
        for (int o = 0; o < 24; o++) {
            float v = 0.f;
            if (o < 6)       v = wcls[(size_t)c * 6 + o];
            else if (o < 18) v = wbox[(size_t)c * 12 + (o - 6)];
            g_wh[o * 512 + c] = __float2half_rn(v);
        }
    }
}

// ---------------------------------------------------------------------------
// conv3x3 + bias + relu + fused 1x1 heads (partials).
// grid (1364, 2), block 256 (8 warps: 2m x 4n), warp tile 64x64.
// ---------------------------------------------------------------------------
__global__ __launch_bounds__(256, 1)
void conv_gemm_kernel(const float* __restrict__ bsh)
{
    extern __shared__ __align__(16) char smem[];
    const uint32_t su = smem_u32(smem);

    const int tid  = threadIdx.x;
    const int wid  = tid >> 5;
    const int lane = tid & 31;
    const int mb   = blockIdx.x;
    const int n0   = blockIdx.y * 256;

    const int l    = lvl_of_blk(mb);
    const int H    = c_H[l];
    const int HH   = H * H;
    const int pixB = c_pixB[l] + (mb - c_blkB[l]) * 128;

    // A loader: 1024 vecs (128 rows x 8 segs of 16B) -> 4/thread
    const int a_seg = tid & 7;
    const int a_r0  = tid >> 3;
    int pb[4], phh[4], pww[4];
#pragma unroll
    for (int i = 0; i < 4; i++) {
        int p = (pixB - c_pixB[l]) + a_r0 + i * 32;
        pb[i] = p / HH; int rem = p - pb[i] * HH;
        phh[i] = rem / H; pww[i] = rem - phh[i] * H;
    }
    const size_t xlevel = (size_t)c_pixB[l] * 256;

    auto issue = [&](int s, int buf) {
        const uint32_t sb = su + buf * STAGE_B;
        int k0 = s * 64;
        int tap = k0 >> 8;
        int kin = k0 & 255;
        int dr = tap / 3 - 1, dc = tap - (tap / 3) * 3 - 1;
#pragma unroll
        for (int i = 0; i < 4; i++) {
            int hh = phh[i] + dr, ww = pww[i] + dc;
            bool ok = ((unsigned)hh < (unsigned)H) && ((unsigned)ww < (unsigned)H);
            const void* src = ok
                ? (const void*)(g_x16 + xlevel
                    + (((size_t)(pb[i] * H + hh)) * H + ww) * 256 + kin + a_seg * 8)
                : (const void*)g_x16;
            cp_async16(sb + (a_r0 + i * 32) * ROW_P + a_seg * 16, src, ok ? 16 : 0);
        }
        // B: 2048 vecs (256 rows x 8 segs) -> 8/thread
#pragma unroll
        for (int i = 0; i < 8; i++) {
            int row = a_r0 + i * 32;
            const void* src = g_wT + (size_t)(n0 + row) * KTOT + k0 + a_seg * 8;
            cp_async16(sb + A_TILE_B + row * ROW_P + a_seg * 16, src, 16);
        }
        cp_commit();
    };

    const int wm = wid >> 2;     // 0..1 -> 64-row group
    const int wn = wid & 3;      // 0..3 -> 64-col group

    float acc[4][8][4];
#pragma unroll
    for (int mi = 0; mi < 4; mi++)
#pragma unroll
        for (int j = 0; j < 8; j++)
#pragma unroll
            for (int e = 0; e < 4; e++) acc[mi][j][e] = 0.f;

    const int la_row = (lane & 15);
    const int la_k   = ((lane >> 4) << 3);
    const int lb_row = ((lane >> 4) << 3) + (lane & 7);
    const int lb_k   = ((lane >> 3) & 1) << 3;

    issue(0, 0);
    issue(1, 1);
#pragma unroll 1
    for (int s = 0; s < NSTAGE; s++) {
        const int buf = s % 3;
        cp_wait1();
        __syncthreads();

        const uint32_t sA = su + buf * STAGE_B;
        const uint32_t sB = sA + A_TILE_B;

        uint32_t af[2][4][4], bf[2][4][4];
        // preload k16 = 0 FIRST (LDSM on critical path), then issue cp.async
#pragma unroll
        for (int mi = 0; mi < 4; mi++)
            ldm_x4(af[0][mi], sA + (wm * 64 + mi * 16 + la_row) * ROW_P + la_k * 2);
#pragma unroll
        for (int q = 0; q < 4; q++)
            ldm_x4(bf[0][q], sB + (wn * 64 + q * 16 + lb_row) * ROW_P + lb_k * 2);

        if (s + 2 < NSTAGE) issue(s + 2, (s + 2) % 3);
        else                cp_commit();

#pragma unroll
        for (int k16 = 0; k16 < 4; k16++) {
            const int cur = k16 & 1;
            if (k16 < 3) {
                const int kk = (k16 + 1) * 16;
#pragma unroll
                for (int mi = 0; mi < 4; mi++)
                    ldm_x4(af[cur ^ 1][mi],
                           sA + (wm * 64 + mi * 16 + la_row) * ROW_P + (kk + la_k) * 2);
#pragma unroll
                for (int q = 0; q < 4; q++)
                    ldm_x4(bf[cur ^ 1][q],
                           sB + (wn * 64 + q * 16 + lb_row) * ROW_P + (kk + lb_k) * 2);
            }
#pragma unroll
            for (int mi = 0; mi < 4; mi++)
#pragma unroll
                for (int j = 0; j < 8; j++)
                    mma16816(acc[mi][j], af[cur][mi],
                             bf[cur][j >> 1][(j & 1) * 2],
                             bf[cur][j >> 1][(j & 1) * 2 + 1]);
        }
    }
    __syncthreads();

    // ---- epilogue 1: bias + relu -> fp16 into ep smem (pitch 528B) ----
    __half* ep = reinterpret_cast<__half*>(smem);   // [128][264]
    const int qr = lane >> 2;
    const int qc = (lane & 3) * 2;
#pragma unroll
    for (int mi = 0; mi < 4; mi++) {
#pragma unroll
        for (int j = 0; j < 8; j++) {
            int col = wn * 64 + j * 8 + qc;
            float b0 = __ldg(bsh + n0 + col);
            float b1 = __ldg(bsh + n0 + col + 1);
            int r0 = wm * 64 + mi * 16 + qr;
            float v0 = fmaxf(acc[mi][j][0] + b0, 0.f);
            float v1 = fmaxf(acc[mi][j][1] + b1, 0.f);
            float v2 = fmaxf(acc[mi][j][2] + b0, 0.f);
            float v3 = fmaxf(acc[mi][j][3] + b1, 0.f);
            *reinterpret_cast<__half2*>(ep + r0 * 264 + col)       = __floats2half2_rn(v0, v1);
            *reinterpret_cast<__half2*>(ep + (r0 + 8) * 264 + col) = __floats2half2_rn(v2, v3);
        }
    }
    // stage head-weight slice [24][256] (pitch 528B)
    for (int i = tid; i < 24 * 32; i += 256) {
        int r = i >> 5, sg = i & 31;
        *reinterpret_cast<uint4*>(smem + WH_OFF + r * EP_PITCH + sg * 16) =
            *reinterpret_cast<const uint4*>(g_wh + r * 512 + n0 + sg * 8);
    }
    __syncthreads();

    // ---- epilogue 2: head GEMM. warp w -> rows w*16..w*16+16, 24 outputs ----
    float ha[3][4];
#pragma unroll
    for (int nt = 0; nt < 3; nt++)
#pragma unroll
        for (int e = 0; e < 4; e++) ha[nt][e] = 0.f;

#pragma unroll
    for (int k16 = 0; k16 < 16; k16++) {
        uint32_t af2[4];
        ldm_x4(af2, su + (wid * 16 + la_row) * EP_PITCH + (k16 * 16 + la_k) * 2);
        int kcol = (k16 * 16 + lb_k) * 2;
        uint32_t b01[4], b2[2];
        ldm_x4(b01, su + WH_OFF + lb_row * EP_PITCH + kcol);
        ldm_x2(b2,  su + WH_OFF + (16 + (lane & 7)) * EP_PITCH + kcol);
        mma16816(ha[0], af2, b01[0], b01[1]);
        mma16816(ha[1], af2, b01[2], b01[3]);
        mma16816(ha[2], af2, b2[0],  b2[1]);
    }

    float* part = g_part[blockIdx.y];
#pragma unroll
    for (int nt = 0; nt < 3; nt++) {
        int c0 = nt * 8 + (lane & 3) * 2;
        if (c0 >= 18) continue;
#pragma unroll
        for (int hrow = 0; hrow < 2; hrow++) {
            int row = wid * 16 + (lane >> 2) + hrow * 8;
            size_t o = (size_t)(pixB + row) * 18 + c0;
            part[o]     = ha[nt][hrow * 2 + 0];
            part[o + 1] = ha[nt][hrow * 2 + 1];
        }
    }
}

// ---------------------------------------------------------------------------
// finalize: sum partials, bias, softmax, scatter
// ---------------------------------------------------------------------------
__global__ __launch_bounds__(256)
void finalize_kernel(const float* __restrict__ bcls, const float* __restrict__ bbox,
                     float* __restrict__ out)
{
    int gp = blockIdx.x * 256 + threadIdx.x;
    if (gp >= TOTM) return;
    int l  = lvl_of_pix(gp);
    int HH = c_H[l] * c_H[l];
    int pl = gp - c_pixB[l];
    int b  = pl / HH;
    int rem = pl - b * HH;

    float v[18];
    const float* q0 = g_part[0] + (size_t)gp * 18;
    const float* q1 = g_part[1] + (size_t)gp * 18;
#pragma unroll
    for (int o = 0; o < 18; o++) v[o] = q0[o] + q1[o];

    float* out_logit = out;
    float* out_prob  = out + (size_t)2 * TOT_POS * 2;
    float* out_box   = out + (size_t)4 * TOT_POS * 2;

#pragma unroll
    for (int a = 0; a < 3; a++) {
        float l0 = v[2 * a]     + bcls[2 * a];
        float l1 = v[2 * a + 1] + bcls[2 * a + 1];
        float mx = fmaxf(l0, l1);
        float e0 = expf(l0 - mx), e1 = expf(l1 - mx);
        float inv = 1.f / (e0 + e1);
        int pos = c_posOff[l] + rem * 3 + a;
        size_t idx = ((size_t)b * TOT_POS + pos) * 2;
        out_logit[idx]     = l0;
        out_logit[idx + 1] = l1;
        out_prob[idx]      = e0 * inv;
        out_prob[idx + 1]  = e1 * inv;
        size_t bidx = ((size_t)b * TOT_POS + pos) * 4;
#pragma unroll
        for (int coord = 0; coord < 4; coord++)
            out_box[bidx + coord] = v[6 + a * 4 + coord] + bbox[a * 4 + coord];
    }
}

// ---------------------------------------------------------------------------
extern "C" void kernel_launch(void* const* d_in, const int* in_sizes, int n_in,
                              void* d_out, int out_size)
{
    const float* p0 = (const float*)d_in[0];
    const float* p1 = (const float*)d_in[1];
    const float* p2 = (const float*)d_in[2];
    const float* p3 = (const float*)d_in[3];
    const float* p4 = (const float*)d_in[4];
    const float* w_share = (const float*)d_in[5];
    const float* b_share = (const float*)d_in[6];
    const float* w_cls   = (const float*)d_in[7];
    const float* b_cls   = (const float*)d_in[8];
    const float* w_box   = (const float*)d_in[9];
    const float* b_box   = (const float*)d_in[10];
    float* out = (float*)d_out;

    cudaFuncSetAttribute(conv_gemm_kernel,
                         cudaFuncAttributeMaxDynamicSharedMemorySize, SMEM_DYN);

    cvt_all_kernel<<<(CVT_TOT + 255) / 256, 256>>>(p0, p1, p2, p3, p4,
                                                   w_share, w_cls, w_box);

    dim3 grid(1364, 2);
    conv_gemm_kernel<<<grid, 256, SMEM_DYN>>>(b_share);

    finalize_kernel<<<(TOTM + 255) / 256, 256>>>(b_cls, b_box, out);
}

// round 15
// speedup vs baseline: 1.0145x; 1.0145x over previous
#include <cuda_runtime.h>
#include <cuda_fp16.h>
#include <cstdint>
#include <cstddef>

// ============================================================================
// RPNHead: single-pass fp16 mma.sync implicit GEMM (K=2304), CTA 128x256,
// 8 warps / warp-tile 64x64, K-stage 64, 3-stage cp.async, 1 sync/stage,
// register-fragment double buffering; cp.async issued AFTER frag preload.
// Heads fused into conv epilogue; finalize sums + softmax + scatter.
// cvt: x = 4x float4/thread (MLP 4); wT = smem tile transpose (coalesced).
// ============================================================================

#define TOTM     174592
#define TOT_POS  261888
#define KTOT     2304            // 9 * 256
#define NSTAGE   36              // KTOT / 64

// conv smem: rows of 64 fp16 = 128B + 16B pad = 144B pitch
#define ROW_P    144
#define A_TILE_B (128 * ROW_P)   // 18432
#define B_TILE_B (256 * ROW_P)   // 36864
#define STAGE_B  (A_TILE_B + B_TILE_B)   // 55296
#define SMEM_DYN (3 * STAGE_B)           // 165888

// epilogue smem layout (reuses stage buffers)
#define EP_PITCH 528             // 264 halfs: 256 data + 8 pad
#define WH_OFF   67584           // after ep tile 128*528

__device__ __align__(16) __half g_x16[(size_t)TOTM * 256];
__device__ __align__(16) __half g_wT [(size_t)512 * KTOT];
__device__ __align__(16) __half g_wh [24 * 512];
__device__ float g_part[2][(size_t)TOTM * 18];

// ---------------------------------------------------------------------------
__device__ __forceinline__ uint32_t smem_u32(const void* p) {
    uint32_t a;
    asm("{ .reg .u64 t; cvta.to.shared.u64 t, %1; cvt.u32.u64 %0, t; }"
        : "=r"(a) : "l"(p));
    return a;
}
__device__ __forceinline__ void cp_async16(uint32_t dst, const void* src, int sz) {
    asm volatile("cp.async.ca.shared.global [%0], [%1], 16, %2;"
                 :: "r"(dst), "l"(src), "r"(sz) : "memory");
}
__device__ __forceinline__ void cp_commit() {
    asm volatile("cp.async.commit_group;" ::: "memory");
}
__device__ __forceinline__ void cp_wait1() {
    asm volatile("cp.async.wait_group 1;" ::: "memory");
}
__device__ __forceinline__ void ldm_x4(uint32_t* r, uint32_t addr) {
    asm volatile("ldmatrix.sync.aligned.m8n8.x4.shared.b16 {%0,%1,%2,%3}, [%4];"
                 : "=r"(r[0]), "=r"(r[1]), "=r"(r[2]), "=r"(r[3]) : "r"(addr));
}
__device__ __forceinline__ void ldm_x2(uint32_t* r, uint32_t addr) {
    asm volatile("ldmatrix.sync.aligned.m8n8.x2.shared.b16 {%0,%1}, [%2];"
                 : "=r"(r[0]), "=r"(r[1]) : "r"(addr));
}
__device__ __forceinline__ void mma16816(float* c, const uint32_t* a,
                                         uint32_t b0, uint32_t b1) {
    asm volatile(
        "mma.sync.aligned.m16n8k16.row.col.f32.f16.f16.f32 "
        "{%0,%1,%2,%3}, {%4,%5,%6,%7}, {%8,%9}, {%0,%1,%2,%3};"
        : "+f"(c[0]), "+f"(c[1]), "+f"(c[2]), "+f"(c[3])
        : "r"(a[0]), "r"(a[1]), "r"(a[2]), "r"(a[3]), "r"(b0), "r"(b1));
}

__device__ __forceinline__ int lvl_of_blk(int mb) {
    return (mb >= 1360) ? 4 : (mb >= 1344) ? 3 : (mb >= 1280) ? 2
         : (mb >= 1024) ? 1 : 0;
}
__device__ __forceinline__ int lvl_of_pix(int gp) {
    return (gp >= 174080) ? 4 : (gp >= 172032) ? 3 : (gp >= 163840) ? 2
         : (gp >= 131072) ? 1 : 0;
}
__constant__ int c_H[5]      = {256, 128, 64, 32, 16};
__constant__ int c_pixB[5]   = {0, 131072, 163840, 172032, 174080};
__constant__ int c_blkB[5]   = {0, 1024, 1280, 1344, 1360};
__constant__ int c_posOff[5] = {0, 196608, 245760, 258048, 261120};

// ---------------------------------------------------------------------------
// cvt 1: x (4x float4/thread, MLP 4) + head weights
// ---------------------------------------------------------------------------
#define CVT_XQ   (TOTM * 16)               // 2793472 quads (each = 4 float4)
#define CVT_TOT  (CVT_XQ + 512)

__global__ __launch_bounds__(256)
void cvt_x_kernel(const float* __restrict__ x0, const float* __restrict__ x1,
                  const float* __restrict__ x2, const float* __restrict__ x3,
                  const float* __restrict__ x4,
                  const float* __restrict__ wcls, const float* __restrict__ wbox)
{
    int i = blockIdx.x * 256 + threadIdx.x;
    if (i < CVT_XQ) {
        int l = (i >= 174080 * 16) ? 4 : (i >= 172032 * 16) ? 3
              : (i >= 163840 * 16) ? 2 : (i >= 131072 * 16) ? 1 : 0;
        const float* xs[5] = {x0, x1, x2, x3, x4};
        const float4* src = reinterpret_cast<const float4*>(xs[l])
                          + ((size_t)i * 4 - (size_t)c_pixB[l] * 64);
        float4 v[4];
#pragma unroll
        for (int j = 0; j < 4; j++) v[j] = src[j];
        uint32_t r[8];
#pragma unroll
        for (int j = 0; j < 4; j++) {
            __half2 h01 = __floats2half2_rn(v[j].x, v[j].y);
            __half2 h23 = __floats2half2_rn(v[j].z, v[j].w);
            r[j * 2]     = *reinterpret_cast<uint32_t*>(&h01);
            r[j * 2 + 1] = *reinterpret_cast<uint32_t*>(&h23);
        }
        uint4* dst = reinterpret_cast<uint4*>(g_x16 + (size_t)i * 16);
        dst[0] = make_uint4(r[0], r[1], r[2], r[3]);
        dst[1] = make_uint4(r[4], r[5], r[6], r[7]);
    } else if (i < CVT_TOT) {
        int c = i - CVT_XQ;                  // 0..511
#pragma unroll
        for (int o = 0; o < 24; o++) {
            float v = 0.f;
            if (o < 6)       v = wcls[(size_t)c * 6 + o];
            else if (o < 18) v = wbox[(size_t)c * 12 + (o - 6)];
            g_wh[o * 512 + c] = __float2half_rn(v);
        }
    }
}

// ---------------------------------------------------------------------------
// cvt 2: w_share^T via smem tile transpose. 288 blocks (36 k-tiles x 8 n-tiles),
// 256 threads. Coalesced loads and stores.
// ---------------------------------------------------------------------------
__global__ __launch_bounds__(256)
void cvt_wT_kernel(const float* __restrict__ wsh)
{
    __shared__ __half t[64][65];
    const int bk = blockIdx.x % 36;     // k tile (64 wide)
    const int bn = blockIdx.x / 36;     // n tile (64 wide)
    const int k0 = bk * 64, n0 = bn * 64;

    const int c  = threadIdx.x & 63;    // n offset on load (coalesced)
    const int r0 = threadIdx.x >> 6;    // 0..3
#pragma unroll
    for (int r = r0; r < 64; r += 4)
        t[r][c] = __float2half_rn(wsh[(size_t)(k0 + r) * 512 + n0 + c]);
    __syncthreads();

    const int kc = threadIdx.x & 7;     // 16B chunk within k (8 halfs)
    const int nr = threadIdx.x >> 3;    // 0..31
#pragma unroll
    for (int n = nr; n < 64; n += 32) {
        __half tmp[8];
#pragma unroll
        for (int j = 0; j < 8; j++) tmp[j] = t[kc * 8 + j][n];
        *reinterpret_cast<uint4*>(g_wT + (size_t)(n0 + n) * KTOT + k0 + kc * 8) =
            *reinterpret_cast<uint4*>(tmp);
    }
}

// ---------------------------------------------------------------------------
// conv3x3 + bias + relu + fused 1x1 heads (partials).
// grid (1364, 2), block 256 (8 warps: 2m x 4n), warp tile 64x64.
// ---------------------------------------------------------------------------
__global__ __launch_bounds__(256, 1)
void conv_gemm_kernel(const float* __restrict__ bsh)
{
    extern __shared__ __align__(16) char smem[];
    const uint32_t su = smem_u32(smem);

    const int tid  = threadIdx.x;
    const int wid  = tid >> 5;
    const int lane = tid & 31;
    const int mb   = blockIdx.x;
    const int n0   = blockIdx.y * 256;

    const int l    = lvl_of_blk(mb);
    const int H    = c_H[l];
    const int HH   = H * H;
    const int pixB = c_pixB[l] + (mb - c_blkB[l]) * 128;

    // A loader: 1024 vecs (128 rows x 8 segs of 16B) -> 4/thread
    const int a_seg = tid & 7;
    const int a_r0  = tid >> 3;
    int pb[4], phh[4], pww[4];
#pragma unroll
    for (int i = 0; i < 4; i++) {
        int p = (pixB - c_pixB[l]) + a_r0 + i * 32;
        pb[i] = p / HH; int rem = p - pb[i] * HH;
        phh[i] = rem / H; pww[i] = rem - phh[i] * H;
    }
    const size_t xlevel = (size_t)c_pixB[l] * 256;

    auto issue = [&](int s, int buf) {
        const uint32_t sb = su + buf * STAGE_B;
        int k0 = s * 64;
        int tap = k0 >> 8;
        int kin = k0 & 255;
        int dr = tap / 3 - 1, dc = tap - (tap / 3) * 3 - 1;
#pragma unroll
        for (int i = 0; i < 4; i++) {
            int hh = phh[i] + dr, ww = pww[i] + dc;
            bool ok = ((unsigned)hh < (unsigned)H) && ((unsigned)ww < (unsigned)H);
            const void* src = ok
                ? (const void*)(g_x16 + xlevel
                    + (((size_t)(pb[i] * H + hh)) * H + ww) * 256 + kin + a_seg * 8)
                : (const void*)g_x16;
            cp_async16(sb + (a_r0 + i * 32) * ROW_P + a_seg * 16, src, ok ? 16 : 0);
        }
        // B: 2048 vecs (256 rows x 8 segs) -> 8/thread
#pragma unroll
        for (int i = 0; i < 8; i++) {
            int row = a_r0 + i * 32;
            const void* src = g_wT + (size_t)(n0 + row) * KTOT + k0 + a_seg * 8;
            cp_async16(sb + A_TILE_B + row * ROW_P + a_seg * 16, src, 16);
        }
        cp_commit();
    };

    const int wm = wid >> 2;     // 0..1 -> 64-row group
    const int wn = wid & 3;      // 0..3 -> 64-col group

    float acc[4][8][4];
#pragma unroll
    for (int mi = 0; mi < 4; mi++)
#pragma unroll
        for (int j = 0; j < 8; j++)
#pragma unroll
            for (int e = 0; e < 4; e++) acc[mi][j][e] = 0.f;

    const int la_row = (lane & 15);
    const int la_k   = ((lane >> 4) << 3);
    const int lb_row = ((lane >> 4) << 3) + (lane & 7);
    const int lb_k   = ((lane >> 3) & 1) << 3;

    issue(0, 0);
    issue(1, 1);
#pragma unroll 1
    for (int s = 0; s < NSTAGE; s++) {
        const int buf = s % 3;
        cp_wait1();
        __syncthreads();

        const uint32_t sA = su + buf * STAGE_B;
        const uint32_t sB = sA + A_TILE_B;

        uint32_t af[2][4][4], bf[2][4][4];
        // preload k16 = 0 FIRST (LDSM on critical path), then issue cp.async
#pragma unroll
        for (int mi = 0; mi < 4; mi++)
            ldm_x4(af[0][mi], sA + (wm * 64 + mi * 16 + la_row) * ROW_P + la_k * 2);
#pragma unroll
        for (int q = 0; q < 4; q++)
            ldm_x4(bf[0][q], sB + (wn * 64 + q * 16 + lb_row) * ROW_P + lb_k * 2);

        if (s + 2 < NSTAGE) issue(s + 2, (s + 2) % 3);
        else                cp_commit();

#pragma unroll
        for (int k16 = 0; k16 < 4; k16++) {
            const int cur = k16 & 1;
            if (k16 < 3) {
                const int kk = (k16 + 1) * 16;
#pragma unroll
                for (int mi = 0; mi < 4; mi++)
                    ldm_x4(af[cur ^ 1][mi],
                           sA + (wm * 64 + mi * 16 + la_row) * ROW_P + (kk + la_k) * 2);
#pragma unroll
                for (int q = 0; q < 4; q++)
                    ldm_x4(bf[cur ^ 1][q],
                           sB + (wn * 64 + q * 16 + lb_row) * ROW_P + (kk + lb_k) * 2);
            }
#pragma unroll
            for (int mi = 0; mi < 4; mi++)
#pragma unroll
                for (int j = 0; j < 8; j++)
                    mma16816(acc[mi][j], af[cur][mi],
                             bf[cur][j >> 1][(j & 1) * 2],
                             bf[cur][j >> 1][(j & 1) * 2 + 1]);
        }
    }
    __syncthreads();

    // ---- epilogue 1: bias + relu -> fp16 into ep smem (pitch 528B) ----
    __half* ep = reinterpret_cast<__half*>(smem);   // [128][264]
    const int qr = lane >> 2;
    const int qc = (lane & 3) * 2;
#pragma unroll
    for (int mi = 0; mi < 4; mi++) {
#pragma unroll
        for (int j = 0; j < 8; j++) {
            int col = wn * 64 + j * 8 + qc;
            float b0 = __ldg(bsh + n0 + col);
            float b1 = __ldg(bsh + n0 + col + 1);
            int r0 = wm * 64 + mi * 16 + qr;
            float v0 = fmaxf(acc[mi][j][0] + b0, 0.f);
            float v1 = fmaxf(acc[mi][j][1] + b1, 0.f);
            float v2 = fmaxf(acc[mi][j][2] + b0, 0.f);
            float v3 = fmaxf(acc[mi][j][3] + b1, 0.f);
            *reinterpret_cast<__half2*>(ep + r0 * 264 + col)       = __floats2half2_rn(v0, v1);
            *reinterpret_cast<__half2*>(ep + (r0 + 8) * 264 + col) = __floats2half2_rn(v2, v3);
        }
    }
    // stage head-weight slice [24][256] (pitch 528B)
    for (int i = tid; i < 24 * 32; i += 256) {
        int r = i >> 5, sg = i & 31;
        *reinterpret_cast<uint4*>(smem + WH_OFF + r * EP_PITCH + sg * 16) =
            *reinterpret_cast<const uint4*>(g_wh + r * 512 + n0 + sg * 8);
    }
    __syncthreads();

    // ---- epilogue 2: head GEMM. warp w -> rows w*16..w*16+16, 24 outputs ----
    float ha[3][4];
#pragma unroll
    for (int nt = 0; nt < 3; nt++)
#pragma unroll
        for (int e = 0; e < 4; e++) ha[nt][e] = 0.f;

#pragma unroll
    for (int k16 = 0; k16 < 16; k16++) {
        uint32_t af2[4];
        ldm_x4(af2, su + (wid * 16 + la_row) * EP_PITCH + (k16 * 16 + la_k) * 2);
        int kcol = (k16 * 16 + lb_k) * 2;
        uint32_t b01[4], b2[2];
        ldm_x4(b01, su + WH_OFF + lb_row * EP_PITCH + kcol);
        ldm_x2(b2,  su + WH_OFF + (16 + (lane & 7)) * EP_PITCH + kcol);
        mma16816(ha[0], af2, b01[0], b01[1]);
        mma16816(ha[1], af2, b01[2], b01[3]);
        mma16816(ha[2], af2, b2[0],  b2[1]);
    }

    float* part = g_part[blockIdx.y];
#pragma unroll
    for (int nt = 0; nt < 3; nt++) {
        int c0 = nt * 8 + (lane & 3) * 2;
        if (c0 >= 18) continue;
#pragma unroll
        for (int hrow = 0; hrow < 2; hrow++) {
            int row = wid * 16 + (lane >> 2) + hrow * 8;
            size_t o = (size_t)(pixB + row) * 18 + c0;
            part[o]     = ha[nt][hrow * 2 + 0];
            part[o + 1] = ha[nt][hrow * 2 + 1];
        }
    }
}

// ---------------------------------------------------------------------------
// finalize: sum partials, bias, softmax, scatter
// ---------------------------------------------------------------------------
__global__ __launch_bounds__(256)
void finalize_kernel(const float* __restrict__ bcls, const float* __restrict__ bbox,
                     float* __restrict__ out)
{
    int gp = blockIdx.x * 256 + threadIdx.x;
    if (gp >= TOTM) return;
    int l  = lvl_of_pix(gp);
    int HH = c_H[l] * c_H[l];
    int pl = gp - c_pixB[l];
    int b  = pl / HH;
    int rem = pl - b * HH;

    float v[18];
    const float* q0 = g_part[0] + (size_t)gp * 18;
    const float* q1 = g_part[1] + (size_t)gp * 18;
#pragma unroll
    for (int o = 0; o < 18; o++) v[o] = q0[o] + q1[o];

    float* out_logit = out;
    float* out_prob  = out + (size_t)2 * TOT_POS * 2;
    float* out_box   = out + (size_t)4 * TOT_POS * 2;

#pragma unroll
    for (int a = 0; a < 3; a++) {
        float l0 = v[2 * a]     + bcls[2 * a];
        float l1 = v[2 * a + 1] + bcls[2 * a + 1];
        float mx = fmaxf(l0, l1);
        float e0 = expf(l0 - mx), e1 = expf(l1 - mx);
        float inv = 1.f / (e0 + e1);
        int pos = c_posOff[l] + rem * 3 + a;
        size_t idx = ((size_t)b * TOT_POS + pos) * 2;
        out_logit[idx]     = l0;
        out_logit[idx + 1] = l1;
        out_prob[idx]      = e0 * inv;
        out_prob[idx + 1]  = e1 * inv;
        size_t bidx = ((size_t)b * TOT_POS + pos) * 4;
#pragma unroll
        for (int coord = 0; coord < 4; coord++)
            out_box[bidx + coord] = v[6 + a * 4 + coord] + bbox[a * 4 + coord];
    }
}

// ---------------------------------------------------------------------------
extern "C" void kernel_launch(void* const* d_in, const int* in_sizes, int n_in,
                              void* d_out, int out_size)
{
    const float* p0 = (const float*)d_in[0];
    const float* p1 = (const float*)d_in[1];
    const float* p2 = (const float*)d_in[2];
    const float* p3 = (const float*)d_in[3];
    const float* p4 = (const float*)d_in[4];
    const float* w_share = (const float*)d_in[5];
    const float* b_share = (const float*)d_in[6];
    const float* w_cls   = (const float*)d_in[7];
    const float* b_cls   = (const float*)d_in[8];
    const float* w_box   = (const float*)d_in[9];
    const float* b_box   = (const float*)d_in[10];
    float* out = (float*)d_out;

    cudaFuncSetAttribute(conv_gemm_kernel,
                         cudaFuncAttributeMaxDynamicSharedMemorySize, SMEM_DYN);

    cvt_wT_kernel<<<288, 256>>>(w_share);
    cvt_x_kernel<<<(CVT_TOT + 255) / 256, 256>>>(p0, p1, p2, p3, p4,
                                                 w_cls, w_box);

    dim3 grid(1364, 2);
    conv_gemm_kernel<<<grid, 256, SMEM_DYN>>>(b_share);

    finalize_kernel<<<(TOTM + 255) / 256, 256>>>(b_cls, b_box, out);
}

// round 16
// speedup vs baseline: 1.0187x; 1.0042x over previous
#include <cuda_runtime.h>
#include <cuda_fp16.h>
#include <cstdint>
#include <cstddef>

// ============================================================================
// RPNHead: single-pass fp16 mma.sync implicit GEMM (K=2304), CTA 128x256,
// 8 warps / warp-tile 64x64, K-stage 64, 3-stage cp.async, 1 sync/stage,
// register-fragment double buffering; cp.async issued AFTER frag preload.
// Heads fused into conv epilogue; partials in SoA layout; finalize coalesced.
// cvt: x = 4x float4/thread (MLP 4); wT = smem tile transpose (coalesced).
// ============================================================================

#define TOTM     174592
#define TOT_POS  261888
#define KTOT     2304            // 9 * 256
#define NSTAGE   36              // KTOT / 64

// conv smem: rows of 64 fp16 = 128B + 16B pad = 144B pitch
#define ROW_P    144
#define A_TILE_B (128 * ROW_P)   // 18432
#define B_TILE_B (256 * ROW_P)   // 36864
#define STAGE_B  (A_TILE_B + B_TILE_B)   // 55296
#define SMEM_DYN (3 * STAGE_B)           // 165888

// epilogue smem layout (reuses stage buffers)
#define EP_PITCH 528             // 264 halfs: 256 data + 8 pad
#define WH_OFF   67584           // after ep tile 128*528

__device__ __align__(16) __half g_x16[(size_t)TOTM * 256];
__device__ __align__(16) __half g_wT [(size_t)512 * KTOT];
__device__ __align__(16) __half g_wh [24 * 512];
// SoA: g_part[half][output_col][pixel]
__device__ float g_part[2][18][(size_t)TOTM];

// ---------------------------------------------------------------------------
__device__ __forceinline__ uint32_t smem_u32(const void* p) {
    uint32_t a;
    asm("{ .reg .u64 t; cvta.to.shared.u64 t, %1; cvt.u32.u64 %0, t; }"
        : "=r"(a) : "l"(p));
    return a;
}
__device__ __forceinline__ void cp_async16(uint32_t dst, const void* src, int sz) {
    asm volatile("cp.async.ca.shared.global [%0], [%1], 16, %2;"
                 :: "r"(dst), "l"(src), "r"(sz) : "memory");
}
__device__ __forceinline__ void cp_commit() {
    asm volatile("cp.async.commit_group;" ::: "memory");
}
__device__ __forceinline__ void cp_wait1() {
    asm volatile("cp.async.wait_group 1;" ::: "memory");
}
__device__ __forceinline__ void ldm_x4(uint32_t* r, uint32_t addr) {
    asm volatile("ldmatrix.sync.aligned.m8n8.x4.shared.b16 {%0,%1,%2,%3}, [%4];"
                 : "=r"(r[0]), "=r"(r[1]), "=r"(r[2]), "=r"(r[3]) : "r"(addr));
}
__device__ __forceinline__ void ldm_x2(uint32_t* r, uint32_t addr) {
    asm volatile("ldmatrix.sync.aligned.m8n8.x2.shared.b16 {%0,%1}, [%2];"
                 : "=r"(r[0]), "=r"(r[1]) : "r"(addr));
}
__device__ __forceinline__ void mma16816(float* c, const uint32_t* a,
                                         uint32_t b0, uint32_t b1) {
    asm volatile(
        "mma.sync.aligned.m16n8k16.row.col.f32.f16.f16.f32 "
        "{%0,%1,%2,%3}, {%4,%5,%6,%7}, {%8,%9}, {%0,%1,%2,%3};"
        : "+f"(c[0]), "+f"(c[1]), "+f"(c[2]), "+f"(c[3])
        : "r"(a[0]), "r"(a[1]), "r"(a[2]), "r"(a[3]), "r"(b0), "r"(b1));
}

__device__ __forceinline__ int lvl_of_blk(int mb) {
    return (mb >= 1360) ? 4 : (mb >= 1344) ? 3 : (mb >= 1280) ? 2
         : (mb >= 1024) ? 1 : 0;
}
__device__ __forceinline__ int lvl_of_pix(int gp) {
    return (gp >= 174080) ? 4 : (gp >= 172032) ? 3 : (gp >= 163840) ? 2
         : (gp >= 131072) ? 1 : 0;
}
__constant__ int c_H[5]      = {256, 128, 64, 32, 16};
__constant__ int c_pixB[5]   = {0, 131072, 163840, 172032, 174080};
__constant__ int c_blkB[5]   = {0, 1024, 1280, 1344, 1360};
__constant__ int c_posOff[5] = {0, 196608, 245760, 258048, 261120};

// ---------------------------------------------------------------------------
// cvt 1: x (4x float4/thread, MLP 4) + head weights
// ---------------------------------------------------------------------------
#define CVT_XQ   (TOTM * 16)               // 2793472 quads (each = 4 float4)
#define CVT_TOT  (CVT_XQ + 512)

__global__ __launch_bounds__(256)
void cvt_x_kernel(const float* __restrict__ x0, const float* __restrict__ x1,
                  const float* __restrict__ x2, const float* __restrict__ x3,
                  const float* __restrict__ x4,
                  const float* __restrict__ wcls, const float* __restrict__ wbox)
{
    int i = blockIdx.x * 256 + threadIdx.x;
    if (i < CVT_XQ) {
        int l = (i >= 174080 * 16) ? 4 : (i >= 172032 * 16) ? 3
              : (i >= 163840 * 16) ? 2 : (i >= 131072 * 16) ? 1 : 0;
        const float* xs[5] = {x0, x1, x2, x3, x4};
        const float4* src = reinterpret_cast<const float4*>(xs[l])
                          + ((size_t)i * 4 - (size_t)c_pixB[l] * 64);
        float4 v[4];
#pragma unroll
        for (int j = 0; j < 4; j++) v[j] = src[j];
        uint32_t r[8];
#pragma unroll
        for (int j = 0; j < 4; j++) {
            __half2 h01 = __floats2half2_rn(v[j].x, v[j].y);
            __half2 h23 = __floats2half2_rn(v[j].z, v[j].w);
            r[j * 2]     = *reinterpret_cast<uint32_t*>(&h01);
            r[j * 2 + 1] = *reinterpret_cast<uint32_t*>(&h23);
        }
        uint4* dst = reinterpret_cast<uint4*>(g_x16 + (size_t)i * 16);
        dst[0] = make_uint4(r[0], r[1], r[2], r[3]);
        dst[1] = make_uint4(r[4], r[5], r[6], r[7]);
    } else if (i < CVT_TOT) {
        int c = i - CVT_XQ;                  // 0..511
#pragma unroll
        for (int o = 0; o < 24; o++) {
            float v = 0.f;
            if (o < 6)       v = wcls[(size_t)c * 6 + o];
            else if (o < 18) v = wbox[(size_t)c * 12 + (o - 6)];
            g_wh[o * 512 + c] = __float2half_rn(v);
        }
    }
}

// ---------------------------------------------------------------------------
// cvt 2: w_share^T via smem tile transpose (coalesced both ways)
// ---------------------------------------------------------------------------
__global__ __launch_bounds__(256)
void cvt_wT_kernel(const float* __restrict__ wsh)
{
    __shared__ __half t[64][65];
    const int bk = blockIdx.x % 36;
    const int bn = blockIdx.x / 36;
    const int k0 = bk * 64, n0 = bn * 64;

    const int c  = threadIdx.x & 63;
    const int r0 = threadIdx.x >> 6;
#pragma unroll
    for (int r = r0; r < 64; r += 4)
        t[r][c] = __float2half_rn(wsh[(size_t)(k0 + r) * 512 + n0 + c]);
    __syncthreads();

    const int kc = threadIdx.x & 7;
    const int nr = threadIdx.x >> 3;
#pragma unroll
    for (int n = nr; n < 64; n += 32) {
        __half tmp[8];
#pragma unroll
        for (int j = 0; j < 8; j++) tmp[j] = t[kc * 8 + j][n];
        *reinterpret_cast<uint4*>(g_wT + (size_t)(n0 + n) * KTOT + k0 + kc * 8) =
            *reinterpret_cast<uint4*>(tmp);
    }
}

// ---------------------------------------------------------------------------
// conv3x3 + bias + relu + fused 1x1 heads (partials, SoA).
// grid (1364, 2), block 256 (8 warps: 2m x 4n), warp tile 64x64.
// ---------------------------------------------------------------------------
__global__ __launch_bounds__(256, 1)
void conv_gemm_kernel(const float* __restrict__ bsh)
{
    extern __shared__ __align__(16) char smem[];
    const uint32_t su = smem_u32(smem);

    const int tid  = threadIdx.x;
    const int wid  = tid >> 5;
    const int lane = tid & 31;
    const int mb   = blockIdx.x;
    const int n0   = blockIdx.y * 256;

    const int l    = lvl_of_blk(mb);
    const int H    = c_H[l];
    const int HH   = H * H;
    const int pixB = c_pixB[l] + (mb - c_blkB[l]) * 128;

    // A loader: 1024 vecs (128 rows x 8 segs of 16B) -> 4/thread
    const int a_seg = tid & 7;
    const int a_r0  = tid >> 3;
    int pb[4], phh[4], pww[4];
#pragma unroll
    for (int i = 0; i < 4; i++) {
        int p = (pixB - c_pixB[l]) + a_r0 + i * 32;
        pb[i] = p / HH; int rem = p - pb[i] * HH;
        phh[i] = rem / H; pww[i] = rem - phh[i] * H;
    }
    const size_t xlevel = (size_t)c_pixB[l] * 256;

    auto issue = [&](int s, int buf) {
        const uint32_t sb = su + buf * STAGE_B;
        int k0 = s * 64;
        int tap = k0 >> 8;
        int kin = k0 & 255;
        int dr = tap / 3 - 1, dc = tap - (tap / 3) * 3 - 1;
#pragma unroll
        for (int i = 0; i < 4; i++) {
            int hh = phh[i] + dr, ww = pww[i] + dc;
            bool ok = ((unsigned)hh < (unsigned)H) && ((unsigned)ww < (unsigned)H);
            const void* src = ok
                ? (const void*)(g_x16 + xlevel
                    + (((size_t)(pb[i] * H + hh)) * H + ww) * 256 + kin + a_seg * 8)
                : (const void*)g_x16;
            cp_async16(sb + (a_r0 + i * 32) * ROW_P + a_seg * 16, src, ok ? 16 : 0);
        }
        // B: 2048 vecs (256 rows x 8 segs) -> 8/thread
#pragma unroll
        for (int i = 0; i < 8; i++) {
            int row = a_r0 + i * 32;
            const void* src = g_wT + (size_t)(n0 + row) * KTOT + k0 + a_seg * 8;
            cp_async16(sb + A_TILE_B + row * ROW_P + a_seg * 16, src, 16);
        }
        cp_commit();
    };

    const int wm = wid >> 2;     // 0..1 -> 64-row group
    const int wn = wid & 3;      // 0..3 -> 64-col group

    float acc[4][8][4];
#pragma unroll
    for (int mi = 0; mi < 4; mi++)
#pragma unroll
        for (int j = 0; j < 8; j++)
#pragma unroll
            for (int e = 0; e < 4; e++) acc[mi][j][e] = 0.f;

    const int la_row = (lane & 15);
    const int la_k   = ((lane >> 4) << 3);
    const int lb_row = ((lane >> 4) << 3) + (lane & 7);
    const int lb_k   = ((lane >> 3) & 1) << 3;

    issue(0, 0);
    issue(1, 1);
#pragma unroll 1
    for (int s = 0; s < NSTAGE; s++) {
        const int buf = s % 3;
        cp_wait1();
        __syncthreads();

        const uint32_t sA = su + buf * STAGE_B;
        const uint32_t sB = sA + A_TILE_B;

        uint32_t af[2][4][4], bf[2][4][4];
        // preload k16 = 0 FIRST (LDSM on critical path), then issue cp.async
#pragma unroll
        for (int mi = 0; mi < 4; mi++)
            ldm_x4(af[0][mi], sA + (wm * 64 + mi * 16 + la_row) * ROW_P + la_k * 2);
#pragma unroll
        for (int q = 0; q < 4; q++)
            ldm_x4(bf[0][q], sB + (wn * 64 + q * 16 + lb_row) * ROW_P + lb_k * 2);

        if (s + 2 < NSTAGE) issue(s + 2, (s + 2) % 3);
        else                cp_commit();

#pragma unroll
        for (int k16 = 0; k16 < 4; k16++) {
            const int cur = k16 & 1;
            if (k16 < 3) {
                const int kk = (k16 + 1) * 16;
#pragma unroll
                for (int mi = 0; mi < 4; mi++)
                    ldm_x4(af[cur ^ 1][mi],
                           sA + (wm * 64 + mi * 16 + la_row) * ROW_P + (kk + la_k) * 2);
#pragma unroll
                for (int q = 0; q < 4; q++)
                    ldm_x4(bf[cur ^ 1][q],
                           sB + (wn * 64 + q * 16 + lb_row) * ROW_P + (kk + lb_k) * 2);
            }
#pragma unroll
            for (int mi = 0; mi < 4; mi++)
#pragma unroll
                for (int j = 0; j < 8; j++)
                    mma16816(acc[mi][j], af[cur][mi],
                             bf[cur][j >> 1][(j & 1) * 2],
                             bf[cur][j >> 1][(j & 1) * 2 + 1]);
        }
    }
    __syncthreads();

    // ---- epilogue 1: bias + relu -> fp16 into ep smem (pitch 528B) ----
    __half* ep = reinterpret_cast<__half*>(smem);   // [128][264]
    const int qr = lane >> 2;
    const int qc = (lane & 3) * 2;
#pragma unroll
    for (int mi = 0; mi < 4; mi++) {
#pragma unroll
        for (int j = 0; j < 8; j++) {
            int col = wn * 64 + j * 8 + qc;
            float b0 = __ldg(bsh + n0 + col);
            float b1 = __ldg(bsh + n0 + col + 1);
            int r0 = wm * 64 + mi * 16 + qr;
            float v0 = fmaxf(acc[mi][j][0] + b0, 0.f);
            float v1 = fmaxf(acc[mi][j][1] + b1, 0.f);
            float v2 = fmaxf(acc[mi][j][2] + b0, 0.f);
            float v3 = fmaxf(acc[mi][j][3] + b1, 0.f);
            *reinterpret_cast<__half2*>(ep + r0 * 264 + col)       = __floats2half2_rn(v0, v1);
            *reinterpret_cast<__half2*>(ep + (r0 + 8) * 264 + col) = __floats2half2_rn(v2, v3);
        }
    }
    // stage head-weight slice [24][256] (pitch 528B)
    for (int i = tid; i < 24 * 32; i += 256) {
        int r = i >> 5, sg = i & 31;
        *reinterpret_cast<uint4*>(smem + WH_OFF + r * EP_PITCH + sg * 16) =
            *reinterpret_cast<const uint4*>(g_wh + r * 512 + n0 + sg * 8);
    }
    __syncthreads();

    // ---- epilogue 2: head GEMM. warp w -> rows w*16..w*16+16, 24 outputs ----
    float ha[3][4];
#pragma unroll
    for (int nt = 0; nt < 3; nt++)
#pragma unroll
        for (int e = 0; e < 4; e++) ha[nt][e] = 0.f;

#pragma unroll
    for (int k16 = 0; k16 < 16; k16++) {
        uint32_t af2[4];
        ldm_x4(af2, su + (wid * 16 + la_row) * EP_PITCH + (k16 * 16 + la_k) * 2);
        int kcol = (k16 * 16 + lb_k) * 2;
        uint32_t b01[4], b2[2];
        ldm_x4(b01, su + WH_OFF + lb_row * EP_PITCH + kcol);
        ldm_x2(b2,  su + WH_OFF + (16 + (lane & 7)) * EP_PITCH + kcol);
        mma16816(ha[0], af2, b01[0], b01[1]);
        mma16816(ha[1], af2, b01[2], b01[3]);
        mma16816(ha[2], af2, b2[0],  b2[1]);
    }

    // SoA partial writes: column-major, 8-lane row runs per column
#pragma unroll
    for (int nt = 0; nt < 3; nt++) {
        int c0 = nt * 8 + (lane & 3) * 2;
        if (c0 >= 18) continue;
#pragma unroll
        for (int hrow = 0; hrow < 2; hrow++) {
            int row = wid * 16 + (lane >> 2) + hrow * 8;
            size_t pix = (size_t)(pixB + row);
            g_part[blockIdx.y][c0][pix]     = ha[nt][hrow * 2 + 0];
            g_part[blockIdx.y][c0 + 1][pix] = ha[nt][hrow * 2 + 1];
        }
    }
}

// ---------------------------------------------------------------------------
// finalize: sum partials (coalesced SoA reads), bias, softmax, scatter
// ---------------------------------------------------------------------------
__global__ __launch_bounds__(256)
void finalize_kernel(const float* __restrict__ bcls, const float* __restrict__ bbox,
                     float* __restrict__ out)
{
    int gp = blockIdx.x * 256 + threadIdx.x;
    if (gp >= TOTM) return;
    int l  = lvl_of_pix(gp);
    int HH = c_H[l] * c_H[l];
    int pl = gp - c_pixB[l];
    int b  = pl / HH;
    int rem = pl - b * HH;

    float v[18];
#pragma unroll
    for (int o = 0; o < 18; o++)
        v[o] = g_part[0][o][gp] + g_part[1][o][gp];

    float* out_logit = out;
    float* out_prob  = out + (size_t)2 * TOT_POS * 2;
    float* out_box   = out + (size_t)4 * TOT_POS * 2;

#pragma unroll
    for (int a = 0; a < 3; a++) {
        float l0 = v[2 * a]     + bcls[2 * a];
        float l1 = v[2 * a + 1] + bcls[2 * a + 1];
        float mx = fmaxf(l0, l1);
        float e0 = expf(l0 - mx), e1 = expf(l1 - mx);
        float inv = 1.f / (e0 + e1);
        int pos = c_posOff[l] + rem * 3 + a;
        size_t idx = ((size_t)b * TOT_POS + pos) * 2;
        out_logit[idx]     = l0;
        out_logit[idx + 1] = l1;
        out_prob[idx]      = e0 * inv;
        out_prob[idx + 1]  = e1 * inv;
        size_t bidx = ((size_t)b * TOT_POS + pos) * 4;
#pragma unroll
        for (int coord = 0; coord < 4; coord++)
            out_box[bidx + coord] = v[6 + a * 4 + coord] + bbox[a * 4 + coord];
    }
}

// ---------------------------------------------------------------------------
extern "C" void kernel_launch(void* const* d_in, const int* in_sizes, int n_in,
                              void* d_out, int out_size)
{
    const float* p0 = (const float*)d_in[0];
    const float* p1 = (const float*)d_in[1];
    const float* p2 = (const float*)d_in[2];
    const float* p3 = (const float*)d_in[3];
    const float* p4 = (const float*)d_in[4];
    const float* w_share = (const float*)d_in[5];
    const float* b_share = (const float*)d_in[6];
    const float* w_cls   = (const float*)d_in[7];
    const float* b_cls   = (const float*)d_in[8];
    const float* w_box   = (const float*)d_in[9];
    const float* b_box   = (const float*)d_in[10];
    float* out = (float*)d_out;

    cudaFuncSetAttribute(conv_gemm_kernel,
                         cudaFuncAttributeMaxDynamicSharedMemorySize, SMEM_DYN);

    cvt_wT_kernel<<<288, 256>>>(w_share);
    cvt_x_kernel<<<(CVT_TOT + 255) / 256, 256>>>(p0, p1, p2, p3, p4,
                                                 w_cls, w_box);

    dim3 grid(1364, 2);
    conv_gemm_kernel<<<grid, 256, SMEM_DYN>>>(b_share);

    finalize_kernel<<<(TOTM + 255) / 256, 256>>>(b_cls, b_box, out);
}

// round 17
// speedup vs baseline: 1.0251x; 1.0063x over previous
#include <cuda_runtime.h>
#include <cuda_fp16.h>
#include <cstdint>
#include <cstddef>

// ============================================================================
// RPNHead: single-pass fp16 mma.sync implicit GEMM (K=2304), CTA 128x256,
// 8 warps / warp-tile 64x64, K-stage 64, 3-stage cp.async, 1 sync/stage,
// register-fragment double buffering; cp.async issued AFTER frag preload.
// Heads fused into conv epilogue; partials SoA; finalize 4 pixels/thread
// fully vectorized. cvt single launch (wT tiles + x quads via block dispatch).
// ============================================================================

#define TOTM     174592
#define TOT_POS  261888
#define KTOT     2304            // 9 * 256
#define NSTAGE   36              // KTOT / 64

// conv smem: rows of 64 fp16 = 128B + 16B pad = 144B pitch
#define ROW_P    144
#define A_TILE_B (128 * ROW_P)   // 18432
#define B_TILE_B (256 * ROW_P)   // 36864
#define STAGE_B  (A_TILE_B + B_TILE_B)   // 55296
#define SMEM_DYN (3 * STAGE_B)           // 165888

// epilogue smem layout (reuses stage buffers)
#define EP_PITCH 528             // 264 halfs: 256 data + 8 pad
#define WH_OFF   67584           // after ep tile 128*528

__device__ __align__(16) __half g_x16[(size_t)TOTM * 256];
__device__ __align__(16) __half g_wT [(size_t)512 * KTOT];
__device__ __align__(16) __half g_wh [24 * 512];
// SoA: g_part[half][output_col][pixel]
__device__ __align__(16) float g_part[2][18][(size_t)TOTM];

// ---------------------------------------------------------------------------
__device__ __forceinline__ uint32_t smem_u32(const void* p) {
    uint32_t a;
    asm("{ .reg .u64 t; cvta.to.shared.u64 t, %1; cvt.u32.u64 %0, t; }"
        : "=r"(a) : "l"(p));
    return a;
}
__device__ __forceinline__ void cp_async16(uint32_t dst, const void* src, int sz) {
    asm volatile("cp.async.ca.shared.global [%0], [%1], 16, %2;"
                 :: "r"(dst), "l"(src), "r"(sz) : "memory");
}
__device__ __forceinline__ void cp_commit() {
    asm volatile("cp.async.commit_group;" ::: "memory");
}
__device__ __forceinline__ void cp_wait1() {
    asm volatile("cp.async.wait_group 1;" ::: "memory");
}
__device__ __forceinline__ void ldm_x4(uint32_t* r, uint32_t addr) {
    asm volatile("ldmatrix.sync.aligned.m8n8.x4.shared.b16 {%0,%1,%2,%3}, [%4];"
                 : "=r"(r[0]), "=r"(r[1]), "=r"(r[2]), "=r"(r[3]) : "r"(addr));
}
__device__ __forceinline__ void ldm_x2(uint32_t* r, uint32_t addr) {
    asm volatile("ldmatrix.sync.aligned.m8n8.x2.shared.b16 {%0,%1}, [%2];"
                 : "=r"(r[0]), "=r"(r[1]) : "r"(addr));
}
__device__ __forceinline__ void mma16816(float* c, const uint32_t* a,
                                         uint32_t b0, uint32_t b1) {
    asm volatile(
        "mma.sync.aligned.m16n8k16.row.col.f32.f16.f16.f32 "
        "{%0,%1,%2,%3}, {%4,%5,%6,%7}, {%8,%9}, {%0,%1,%2,%3};"
        : "+f"(c[0]), "+f"(c[1]), "+f"(c[2]), "+f"(c[3])
        : "r"(a[0]), "r"(a[1]), "r"(a[2]), "r"(a[3]), "r"(b0), "r"(b1));
}

__device__ __forceinline__ int lvl_of_blk(int mb) {
    return (mb >= 1360) ? 4 : (mb >= 1344) ? 3 : (mb >= 1280) ? 2
         : (mb >= 1024) ? 1 : 0;
}
__constant__ int c_H[5]      = {256, 128, 64, 32, 16};
__constant__ int c_pixB[5]   = {0, 131072, 163840, 172032, 174080};
__constant__ int c_blkB[5]   = {0, 1024, 1280, 1344, 1360};
__constant__ int c_posOff[5] = {0, 196608, 245760, 258048, 261120};

// ---------------------------------------------------------------------------
// cvt (single launch): blocks 0..287 = wT tile transpose;
// blocks 288.. = x quads (MLP 4) + head weights.
// ---------------------------------------------------------------------------
#define CVT_WT_BLKS 288
#define CVT_XQ   (TOTM * 16)               // quads (each = 4 float4)
#define CVT_TOT  (CVT_XQ + 512)
#define CVT_BLKS (CVT_WT_BLKS + (CVT_TOT + 255) / 256)

__global__ __launch_bounds__(256)
void cvt_all_kernel(const float* __restrict__ x0, const float* __restrict__ x1,
                    const float* __restrict__ x2, const float* __restrict__ x3,
                    const float* __restrict__ x4,
                    const float* __restrict__ wsh,
                    const float* __restrict__ wcls, const float* __restrict__ wbox)
{
    if (blockIdx.x < CVT_WT_BLKS) {
        // ---- w_share^T tile transpose (coalesced both ways) ----
        __shared__ __half t[64][65];
        const int bk = blockIdx.x % 36;
        const int bn = blockIdx.x / 36;
        const int k0 = bk * 64, n0 = bn * 64;

        const int c  = threadIdx.x & 63;
        const int r0 = threadIdx.x >> 6;
#pragma unroll
        for (int r = r0; r < 64; r += 4)
            t[r][c] = __float2half_rn(wsh[(size_t)(k0 + r) * 512 + n0 + c]);
        __syncthreads();

        const int kc = threadIdx.x & 7;
        const int nr = threadIdx.x >> 3;
#pragma unroll
        for (int n = nr; n < 64; n += 32) {
            __half tmp[8];
#pragma unroll
            for (int j = 0; j < 8; j++) tmp[j] = t[kc * 8 + j][n];
            *reinterpret_cast<uint4*>(g_wT + (size_t)(n0 + n) * KTOT + k0 + kc * 8) =
                *reinterpret_cast<uint4*>(tmp);
        }
        return;
    }

    int i = (blockIdx.x - CVT_WT_BLKS) * 256 + threadIdx.x;
    if (i < CVT_XQ) {
        int l = (i >= 174080 * 16) ? 4 : (i >= 172032 * 16) ? 3
              : (i >= 163840 * 16) ? 2 : (i >= 131072 * 16) ? 1 : 0;
        const float* xs[5] = {x0, x1, x2, x3, x4};
        const float4* src = reinterpret_cast<const float4*>(xs[l])
                          + ((size_t)i * 4 - (size_t)c_pixB[l] * 64);
        float4 v[4];
#pragma unroll
        for (int j = 0; j < 4; j++) v[j] = src[j];
        uint32_t r[8];
#pragma unroll
        for (int j = 0; j < 4; j++) {
            __half2 h01 = __floats2half2_rn(v[j].x, v[j].y);
            __half2 h23 = __floats2half2_rn(v[j].z, v[j].w);
            r[j * 2]     = *reinterpret_cast<uint32_t*>(&h01);
            r[j * 2 + 1] = *reinterpret_cast<uint32_t*>(&h23);
        }
        uint4* dst = reinterpret_cast<uint4*>(g_x16 + (size_t)i * 16);
        dst[0] = make_uint4(r[0], r[1], r[2], r[3]);
        dst[1] = make_uint4(r[4], r[5], r[6], r[7]);
    } else if (i < CVT_TOT) {
        int c = i - CVT_XQ;                  // 0..511
#pragma unroll
        for (int o = 0; o < 24; o++) {
            float v = 0.f;
            if (o < 6)       v = wcls[(size_t)c * 6 + o];
            else if (o < 18) v = wbox[(size_t)c * 12 + (o - 6)];
            g_wh[o * 512 + c] = __float2half_rn(v);
        }
    }
}

// ---------------------------------------------------------------------------
// conv3x3 + bias + relu + fused 1x1 heads (partials, SoA).
// grid (1364, 2), block 256 (8 warps: 2m x 4n), warp tile 64x64.
// ---------------------------------------------------------------------------
__global__ __launch_bounds__(256, 1)
void conv_gemm_kernel(const float* __restrict__ bsh)
{
    extern __shared__ __align__(16) char smem[];
    const uint32_t su = smem_u32(smem);

    const int tid  = threadIdx.x;
    const int wid  = tid >> 5;
    const int lane = tid & 31;
    const int mb   = blockIdx.x;
    const int n0   = blockIdx.y * 256;

    const int l    = lvl_of_blk(mb);
    const int H    = c_H[l];
    const int HH   = H * H;
    const int pixB = c_pixB[l] + (mb - c_blkB[l]) * 128;

    // A loader: 1024 vecs (128 rows x 8 segs of 16B) -> 4/thread
    const int a_seg = tid & 7;
    const int a_r0  = tid >> 3;
    int pb[4], phh[4], pww[4];
#pragma unroll
    for (int i = 0; i < 4; i++) {
        int p = (pixB - c_pixB[l]) + a_r0 + i * 32;
        pb[i] = p / HH; int rem = p - pb[i] * HH;
        phh[i] = rem / H; pww[i] = rem - phh[i] * H;
    }
    const size_t xlevel = (size_t)c_pixB[l] * 256;

    auto issue = [&](int s, int buf) {
        const uint32_t sb = su + buf * STAGE_B;
        int k0 = s * 64;
        int tap = k0 >> 8;
        int kin = k0 & 255;
        int dr = tap / 3 - 1, dc = tap - (tap / 3) * 3 - 1;
#pragma unroll
        for (int i = 0; i < 4; i++) {
            int hh = phh[i] + dr, ww = pww[i] + dc;
            bool ok = ((unsigned)hh < (unsigned)H) && ((unsigned)ww < (unsigned)H);
            const void* src = ok
                ? (const void*)(g_x16 + xlevel
                    + (((size_t)(pb[i] * H + hh)) * H + ww) * 256 + kin + a_seg * 8)
                : (const void*)g_x16;
            cp_async16(sb + (a_r0 + i * 32) * ROW_P + a_seg * 16, src, ok ? 16 : 0);
        }
        // B: 2048 vecs (256 rows x 8 segs) -> 8/thread
#pragma unroll
        for (int i = 0; i < 8; i++) {
            int row = a_r0 + i * 32;
            const void* src = g_wT + (size_t)(n0 + row) * KTOT + k0 + a_seg * 8;
            cp_async16(sb + A_TILE_B + row * ROW_P + a_seg * 16, src, 16);
        }
        cp_commit();
    };

    const int wm = wid >> 2;     // 0..1 -> 64-row group
    const int wn = wid & 3;      // 0..3 -> 64-col group

    float acc[4][8][4];
#pragma unroll
    for (int mi = 0; mi < 4; mi++)
#pragma unroll
        for (int j = 0; j < 8; j++)
#pragma unroll
            for (int e = 0; e < 4; e++) acc[mi][j][e] = 0.f;

    const int la_row = (lane & 15);
    const int la_k   = ((lane >> 4) << 3);
    const int lb_row = ((lane >> 4) << 3) + (lane & 7);
    const int lb_k   = ((lane >> 3) & 1) << 3;

    issue(0, 0);
    issue(1, 1);
#pragma unroll 1
    for (int s = 0; s < NSTAGE; s++) {
        const int buf = s % 3;
        cp_wait1();
        __syncthreads();

        const uint32_t sA = su + buf * STAGE_B;
        const uint32_t sB = sA + A_TILE_B;

        uint32_t af[2][4][4], bf[2][4][4];
        // preload k16 = 0 FIRST (LDSM on critical path), then issue cp.async
#pragma unroll
        for (int mi = 0; mi < 4; mi++)
            ldm_x4(af[0][mi], sA + (wm * 64 + mi * 16 + la_row) * ROW_P + la_k * 2);
#pragma unroll
        for (int q = 0; q < 4; q++)
            ldm_x4(bf[0][q], sB + (wn * 64 + q * 16 + lb_row) * ROW_P + lb_k * 2);

        if (s + 2 < NSTAGE) issue(s + 2, (s + 2) % 3);
        else                cp_commit();

#pragma unroll
        for (int k16 = 0; k16 < 4; k16++) {
            const int cur = k16 & 1;
            if (k16 < 3) {
                const int kk = (k16 + 1) * 16;
#pragma unroll
                for (int mi = 0; mi < 4; mi++)
                    ldm_x4(af[cur ^ 1][mi],
                           sA + (wm * 64 + mi * 16 + la_row) * ROW_P + (kk + la_k) * 2);
#pragma unroll
                for (int q = 0; q < 4; q++)
                    ldm_x4(bf[cur ^ 1][q],
                           sB + (wn * 64 + q * 16 + lb_row) * ROW_P + (kk + lb_k) * 2);
            }
#pragma unroll
            for (int mi = 0; mi < 4; mi++)
#pragma unroll
                for (int j = 0; j < 8; j++)
                    mma16816(acc[mi][j], af[cur][mi],
                             bf[cur][j >> 1][(j & 1) * 2],
                             bf[cur][j >> 1][(j & 1) * 2 + 1]);
        }
    }
    __syncthreads();

    // ---- epilogue 1: bias + relu -> fp16 into ep smem (pitch 528B) ----
    __half* ep = reinterpret_cast<__half*>(smem);   // [128][264]
    const int qr = lane >> 2;
    const int qc = (lane & 3) * 2;
#pragma unroll
    for (int mi = 0; mi < 4; mi++) {
#pragma unroll
        for (int j = 0; j < 8; j++) {
            int col = wn * 64 + j * 8 + qc;
            float b0 = __ldg(bsh + n0 + col);
            float b1 = __ldg(bsh + n0 + col + 1);
            int r0 = wm * 64 + mi * 16 + qr;
            float v0 = fmaxf(acc[mi][j][0] + b0, 0.f);
            float v1 = fmaxf(acc[mi][j][1] + b1, 0.f);
            float v2 = fmaxf(acc[mi][j][2] + b0, 0.f);
            float v3 = fmaxf(acc[mi][j][3] + b1, 0.f);
            *reinterpret_cast<__half2*>(ep + r0 * 264 + col)       = __floats2half2_rn(v0, v1);
            *reinterpret_cast<__half2*>(ep + (r0 + 8) * 264 + col) = __floats2half2_rn(v2, v3);
        }
    }
    // stage head-weight slice [24][256] (pitch 528B)
    for (int i = tid; i < 24 * 32; i += 256) {
        int r = i >> 5, sg = i & 31;
        *reinterpret_cast<uint4*>(smem + WH_OFF + r * EP_PITCH + sg * 16) =
            *reinterpret_cast<const uint4*>(g_wh + r * 512 + n0 + sg * 8);
    }
    __syncthreads();

    // ---- epilogue 2: head GEMM. warp w -> rows w*16..w*16+16, 24 outputs ----
    float ha[3][4];
#pragma unroll
    for (int nt = 0; nt < 3; nt++)
#pragma unroll
        for (int e = 0; e < 4; e++) ha[nt][e] = 0.f;

#pragma unroll
    for (int k16 = 0; k16 < 16; k16++) {
        uint32_t af2[4];
        ldm_x4(af2, su + (wid * 16 + la_row) * EP_PITCH + (k16 * 16 + la_k) * 2);
        int kcol = (k16 * 16 + lb_k) * 2;
        uint32_t b01[4], b2[2];
        ldm_x4(b01, su + WH_OFF + lb_row * EP_PITCH + kcol);
        ldm_x2(b2,  su + WH_OFF + (16 + (lane & 7)) * EP_PITCH + kcol);
        mma16816(ha[0], af2, b01[0], b01[1]);
        mma16816(ha[1], af2, b01[2], b01[3]);
        mma16816(ha[2], af2, b2[0],  b2[1]);
    }

    // SoA partial writes
#pragma unroll
    for (int nt = 0; nt < 3; nt++) {
        int c0 = nt * 8 + (lane & 3) * 2;
        if (c0 >= 18) continue;
#pragma unroll
        for (int hrow = 0; hrow < 2; hrow++) {
            int row = wid * 16 + (lane >> 2) + hrow * 8;
            size_t pix = (size_t)(pixB + row);
            g_part[blockIdx.y][c0][pix]     = ha[nt][hrow * 2 + 0];
            g_part[blockIdx.y][c0 + 1][pix] = ha[nt][hrow * 2 + 1];
        }
    }
}

// ---------------------------------------------------------------------------
// finalize: 4 pixels/thread, float4 reads (MLP 36) + float4 writes.
// Quads never straddle level/batch boundaries (pixB, HH multiples of 4).
// ---------------------------------------------------------------------------
__global__ __launch_bounds__(256)
void finalize_kernel(const float* __restrict__ bcls, const float* __restrict__ bbox,
                     float* __restrict__ out)
{
    int q = blockIdx.x * 256 + threadIdx.x;
    if (q >= TOTM / 4) return;
    int gp = q * 4;
    int l  = (gp >= 174080) ? 4 : (gp >= 172032) ? 3 : (gp >= 163840) ? 2
           : (gp >= 131072) ? 1 : 0;
    int HH = c_H[l] * c_H[l];
    int pl = gp - c_pixB[l];
    int b  = pl / HH;
    int rem = pl - b * HH;       // multiple of 4

    // v[o] = per-column float4 (4 consecutive pixels), summed over halves
    float4 v[18];
#pragma unroll
    for (int o = 0; o < 18; o++) {
        float4 a = *reinterpret_cast<const float4*>(&g_part[0][o][gp]);
        float4 c = *reinterpret_cast<const float4*>(&g_part[1][o][gp]);
        v[o] = make_float4(a.x + c.x, a.y + c.y, a.z + c.z, a.w + c.w);
    }

    float bc[6], bb[12];
#pragma unroll
    for (int o = 0; o < 6; o++)  bc[o] = bcls[o];
#pragma unroll
    for (int o = 0; o < 12; o++) bb[o] = bbox[o];

    float* out_logit = out;
    float* out_prob  = out + (size_t)2 * TOT_POS * 2;
    float* out_box   = out + (size_t)4 * TOT_POS * 2;

    int pos0 = c_posOff[l] + rem * 3;             // 12 consecutive positions
    size_t lbase = ((size_t)b * TOT_POS + pos0) * 2;   // 24 floats, 16B aligned
    size_t bbase = ((size_t)b * TOT_POS + pos0) * 4;   // 48 floats, 16B aligned

    float lg[24], pr[24], bx[48];
#pragma unroll
    for (int px = 0; px < 4; px++) {
        const float* vp = reinterpret_cast<const float*>(v);  // v[o] field px
#pragma unroll
        for (int a = 0; a < 3; a++) {
            float l0 = reinterpret_cast<const float*>(&v[2 * a])[px]     + bc[2 * a];
            float l1 = reinterpret_cast<const float*>(&v[2 * a + 1])[px] + bc[2 * a + 1];
            float mx = fmaxf(l0, l1);
            float e0 = expf(l0 - mx), e1 = expf(l1 - mx);
            float inv = 1.f / (e0 + e1);
            int o2 = px * 6 + a * 2;
            lg[o2]     = l0;  lg[o2 + 1] = l1;
            pr[o2]     = e0 * inv; pr[o2 + 1] = e1 * inv;
#pragma unroll
            for (int coord = 0; coord < 4; coord++)
                bx[px * 12 + a * 4 + coord] =
                    reinterpret_cast<const float*>(&v[6 + a * 4 + coord])[px]
                    + bb[a * 4 + coord];
        }
        (void)vp;
    }
#pragma unroll
    for (int j = 0; j < 6; j++) {
        *reinterpret_cast<float4*>(out_logit + lbase + j * 4) =
            *reinterpret_cast<float4*>(lg + j * 4);
        *reinterpret_cast<float4*>(out_prob + lbase + j * 4) =
            *reinterpret_cast<float4*>(pr + j * 4);
    }
#pragma unroll
    for (int j = 0; j < 12; j++)
        *reinterpret_cast<float4*>(out_box + bbase + j * 4) =
            *reinterpret_cast<float4*>(bx + j * 4);
}

// ---------------------------------------------------------------------------
extern "C" void kernel_launch(void* const* d_in, const int* in_sizes, int n_in,
                              void* d_out, int out_size)
{
    const float* p0 = (const float*)d_in[0];
    const float* p1 = (const float*)d_in[1];
    const float* p2 = (const float*)d_in[2];
    const float* p3 = (const float*)d_in[3];
    const float* p4 = (const float*)d_in[4];
    const float* w_share = (const float*)d_in[5];
    const float* b_share = (const float*)d_in[6];
    const float* w_cls   = (const float*)d_in[7];
    const float* b_cls   = (const float*)d_in[8];
    const float* w_box   = (const float*)d_in[9];
    const float* b_box   = (const float*)d_in[10];
    float* out = (float*)d_out;

    cudaFuncSetAttribute(conv_gemm_kernel,
                         cudaFuncAttributeMaxDynamicSharedMemorySize, SMEM_DYN);

    cvt_all_kernel<<<CVT_BLKS, 256>>>(p0, p1, p2, p3, p4,
                                      w_share, w_cls, w_box);

    dim3 grid(1364, 2);
    conv_gemm_kernel<<<grid, 256, SMEM_DYN>>>(b_share);

    finalize_kernel<<<(TOTM / 4 + 255) / 256, 256>>>(b_cls, b_box, out);
}